// round 16
// baseline (speedup 1.0000x reference)
#include <cuda_runtime.h>
#include <cuda_bf16.h>
#include <math.h>
#include <stdint.h>

namespace sg {
constexpr int Bn = 8, Cc = 256, Nn = 16;
constexpr int HW = 384;
constexpr int C32 = 384;
constexpr float SCALE = 1.0f / 16.0f;
constexpr float IMGW = 384.0f, IMGH = 256.0f;
constexpr int PP = 49;
constexpr int KFC = 12544;
constexpr int SPLK = 7;               // rel FC split-K (7*1792 = 12544)
constexpr int SPLKO = 49;
constexpr int NPAIRU = 136;

constexpr long SZ_CTXF  = (long)Bn * Cc * HW;
constexpr long SZ_RELF  = (long)Bn * C32 * HW;
constexpr long SZ_FEATT = SZ_CTXF;
constexpr long SZ_RELFT = SZ_RELF;
constexpr long SZ_PCTX4 = (long)Bn * 4 * Cc * PP;
constexpr long SZ_BIMAP = (long)Bn * Nn * PP;
constexpr long SZ_XOBJ  = (long)Bn * 512 * 784;
constexpr long SZ_OBJ   = (long)Bn * 256 * 784;
constexpr long SZ_ASUB  = SZ_OBJ;
constexpr long SZ_AOBJ  = SZ_OBJ;
constexpr long SZ_FREL  = 256L * 2048;
constexpr long SZ_FOBJ  = 256L * 128;
constexpr long SZ_FP    = 14L * 256 * 2048;
constexpr long SZ_FPO   = (long)SPLKO * 256 * 128;
constexpr long FU_WP  = 256L * 384 / 2;
constexpr long FU_XRT = (long)Bn * KFC * 384 / 2;
constexpr long FU_WR  = 256L * KFC / 2;
constexpr long FU_RT  = 2048L * KFC / 2;
constexpr long FU_WO  = FU_WR;
constexpr long FU_RO  = 128L * KFC / 2;

constexpr long OF_CTXF  = 0;
constexpr long OF_RELF  = OF_CTXF  + SZ_CTXF;
constexpr long OF_FEATT = OF_RELF  + SZ_RELF;
constexpr long OF_RELFT = OF_FEATT + SZ_FEATT;
constexpr long OF_PCTX4 = OF_RELFT + SZ_RELFT;
constexpr long OF_BIMAP = OF_PCTX4 + SZ_PCTX4;
constexpr long OF_XOBJ  = OF_BIMAP + SZ_BIMAP;
constexpr long OF_OBJ   = OF_XOBJ  + SZ_XOBJ;
constexpr long OF_ASUB  = OF_OBJ   + SZ_OBJ;
constexpr long OF_AOBJ  = OF_ASUB  + SZ_ASUB;
constexpr long OF_FREL  = OF_AOBJ  + SZ_AOBJ;
constexpr long OF_FOBJ  = OF_FREL  + SZ_FREL;
constexpr long OF_FP    = OF_FOBJ  + SZ_FOBJ;
constexpr long OF_FPO   = OF_FP    + SZ_FP;
constexpr long OF_WPH   = OF_FPO   + SZ_FPO;
constexpr long OF_WPL   = OF_WPH   + FU_WP;
constexpr long OF_XRTH  = OF_WPL   + FU_WP;
constexpr long OF_XRTL  = OF_XRTH  + FU_XRT;
constexpr long OF_WRH   = OF_XRTL  + FU_XRT;
constexpr long OF_WRL   = OF_WRH   + FU_WR;
constexpr long OF_RTH   = OF_WRL   + FU_WR;
constexpr long OF_RTL   = OF_RTH   + FU_RT;
constexpr long OF_WOH   = OF_RTL   + FU_RT;
constexpr long OF_WOL   = OF_WOH   + FU_WO;
constexpr long OF_ROH   = OF_WOL   + FU_WO;
constexpr long OF_ROL   = OF_ROH   + FU_RO;
constexpr long TOTAL    = OF_ROL   + FU_RO + 64;
}  // namespace sg

__device__ float g_buf[sg::TOTAL];

// ========================= low-level helpers ===============================
__device__ __forceinline__ uint32_t smem_u32(const void* p) {
    uint32_t a;
    asm("{ .reg .u64 t; cvta.to.shared.u64 t, %1; cvt.u32.u64 %0, t; }" : "=r"(a) : "l"(p));
    return a;
}
__device__ __forceinline__ void cp_async16(uint32_t dst, const void* src) {
    asm volatile("cp.async.cg.shared.global [%0], [%1], 16;" :: "r"(dst), "l"(src));
}
__device__ __forceinline__ void cp_commit() {
    asm volatile("cp.async.commit_group;" ::: "memory");
}
__device__ __forceinline__ void ldsm4(uint32_t* a, uint32_t addr) {
    asm volatile("ldmatrix.sync.aligned.m8n8.x4.shared.b16 {%0,%1,%2,%3}, [%4];"
        : "=r"(a[0]), "=r"(a[1]), "=r"(a[2]), "=r"(a[3]) : "r"(addr));
}
__device__ __forceinline__ void ldsm2(uint32_t* b, uint32_t addr) {
    asm volatile("ldmatrix.sync.aligned.m8n8.x2.shared.b16 {%0,%1}, [%2];"
        : "=r"(b[0]), "=r"(b[1]) : "r"(addr));
}
__device__ __forceinline__ void mma16816(float* d, const uint32_t* a, const uint32_t* b) {
    asm volatile("mma.sync.aligned.m16n8k16.row.col.f32.bf16.bf16.f32 "
        "{%0,%1,%2,%3}, {%4,%5,%6,%7}, {%8,%9}, {%0,%1,%2,%3};"
        : "+f"(d[0]), "+f"(d[1]), "+f"(d[2]), "+f"(d[3])
        : "r"(a[0]), "r"(a[1]), "r"(a[2]), "r"(a[3]), "r"(b[0]), "r"(b[1]));
}
__device__ __forceinline__ void split_bf16(float x, __nv_bfloat16& h, __nv_bfloat16& l) {
    h = __float2bfloat16(x);
    l = __float2bfloat16(x - __bfloat162float(h));
}

// ========================= PrRoI pooling helpers ===========================
static __device__ __forceinline__ float hatG(float t) {
    float tl = fminf(fmaxf(t, -1.0f), 0.0f);
    float tr = fminf(fmaxf(t, 0.0f), 1.0f);
    return 0.5f * (tl + 1.0f) * (tl + 1.0f) + 0.5f - 0.5f * (1.0f - tr) * (1.0f - tr);
}

static __device__ __forceinline__ void compute_weights(
    float x1, float y1, float x2, float y2,
    float (*wy)[16], float (*wx)[32],
    int* h0, int* h1, int* w0, int* w1, int tid)
{
    if (tid < 112) {
        int p = tid / 16, i = tid % 16;
        float e0 = y1 + (y2 - y1) * (float)p * (1.0f / 7.0f);
        float e1 = y1 + (y2 - y1) * (float)(p + 1) * (1.0f / 7.0f);
        wy[p][i] = hatG(e1 - (float)i) - hatG(e0 - (float)i);
    }
    if (tid < 224) {
        int q = tid >> 5, i = tid & 31;
        float v = 0.0f;
        if (i < 24) {
            float e0 = x1 + (x2 - x1) * (float)q * (1.0f / 7.0f);
            float e1 = x1 + (x2 - x1) * (float)(q + 1) * (1.0f / 7.0f);
            v = hatG(e1 - (float)i) - hatG(e0 - (float)i);
        }
        wx[q][i] = v;
    }
    if (tid < 7) {
        float e0 = y1 + (y2 - y1) * (float)tid * (1.0f / 7.0f);
        float e1 = y1 + (y2 - y1) * (float)(tid + 1) * (1.0f / 7.0f);
        h0[tid] = max(0, (int)ceilf(e0) - 1);
        h1[tid] = min(16, (int)floorf(e1) + 2);
    }
    if (tid >= 32 && tid < 39) {
        int q = tid - 32;
        float e0 = x1 + (x2 - x1) * (float)q * (1.0f / 7.0f);
        float e1 = x1 + (x2 - x1) * (float)(q + 1) * (1.0f / 7.0f);
        w0[q] = max(0, (int)ceilf(e0) - 1);
        w1[q] = min(24, (int)floorf(e1) + 2);
    }
}

static __device__ __forceinline__ void pool_channel_acc_range(
    const float* __restrict__ fb, int ps,
    const float (*wy)[16], const float (*wx)[32],
    const int* w0,
    int hlo, int hhi, float* acc)
{
    for (int h = hlo; h < hhi; h++) {
        const float* row = fb + (long)h * 24 * ps;
        float colsum[7];
#pragma unroll
        for (int q = 0; q < 7; q++) {
            int base = w0[q];
            const float* rp = row + (long)base * ps;
            float a = 0.0f;
#pragma unroll
            for (int k = 0; k < 6; k++)
                a += wx[q][base + k] * rp[(long)k * ps];
            colsum[q] = a;
        }
#pragma unroll
        for (int p = 0; p < 7; p++) {
            float wv = wy[p][h];
#pragma unroll
            for (int q = 0; q < 7; q++)
                acc[p * 7 + q] += wv * colsum[q];
        }
    }
}

// ===================== dual 1x1 conv (yOff-chunked) ========================
__global__ void __launch_bounds__(256) conv_dual_kernel(
    const float* __restrict__ input,
    const float* __restrict__ Wctx, const float* __restrict__ bctx,
    const float* __restrict__ Wrel, const float* __restrict__ brel,
    int yOff)
{
    using namespace sg;
    __shared__ float As[16][65];
    __shared__ float Bs[16][68];

    const int b = blockIdx.z;
    const int tid = threadIdx.x;
    const int row0 = (blockIdx.y + yOff) * 64;
    const int col0 = blockIdx.x * 64;
    const bool isCtx = row0 < 256;
    const float* A = isCtx ? (Wctx + (long)row0 * 256)
                           : (Wrel + (long)(row0 - 256) * 256);
    const float* bias = isCtx ? bctx : brel;
    const int biasBase = isCtx ? row0 : row0 - 256;
    const float* Bm = input + (long)b * Cc * HW;
    float* Cm = isCtx ? (g_buf + OF_CTXF + (long)b * Cc * HW + (long)row0 * 384)
                      : (g_buf + OF_RELF + (long)b * C32 * HW + (long)(row0 - 256) * 384);

    const int ty = tid >> 4, tx = tid & 15;
    const int ty4 = ty * 4, tx4 = tx * 4;
    const int ar = tid >> 2, ak = (tid & 3) << 2;
    const int br = tid >> 4, bc = (tid & 15) << 2;

    float acc[4][4] = {};

    for (int k0 = 0; k0 < 256; k0 += 16) {
        float4 av = *(const float4*)(A + (long)ar * 256 + k0 + ak);
        As[ak + 0][ar] = av.x; As[ak + 1][ar] = av.y;
        As[ak + 2][ar] = av.z; As[ak + 3][ar] = av.w;
        float4 bv = *(const float4*)(Bm + (long)(k0 + br) * 384 + col0 + bc);
        *(float4*)&Bs[br][bc] = bv;
        __syncthreads();

#pragma unroll
        for (int k = 0; k < 16; k++) {
            float a0 = As[k][ty4 + 0], a1 = As[k][ty4 + 1];
            float a2 = As[k][ty4 + 2], a3 = As[k][ty4 + 3];
            float4 b4 = *(const float4*)&Bs[k][tx4];
            acc[0][0] += a0 * b4.x; acc[0][1] += a0 * b4.y; acc[0][2] += a0 * b4.z; acc[0][3] += a0 * b4.w;
            acc[1][0] += a1 * b4.x; acc[1][1] += a1 * b4.y; acc[1][2] += a1 * b4.z; acc[1][3] += a1 * b4.w;
            acc[2][0] += a2 * b4.x; acc[2][1] += a2 * b4.y; acc[2][2] += a2 * b4.z; acc[2][3] += a2 * b4.w;
            acc[3][0] += a3 * b4.x; acc[3][1] += a3 * b4.y; acc[3][2] += a3 * b4.z; acc[3][3] += a3 * b4.w;
        }
        __syncthreads();
    }

#pragma unroll
    for (int u = 0; u < 4; u++) {
        float bz = bias[biasBase + ty4 + u];
#pragma unroll
        for (int v = 0; v < 4; v++)
            Cm[(long)(ty4 + u) * 384 + col0 + tx4 + v] = acc[u][v] + bz;
    }
}

// fp32 128x128 GEMM, optional multi-term via grid.y folding.
__global__ void __launch_bounds__(256) sgemm128_kernel(
    const float* __restrict__ Aex, long offA, int lda,
    long offB, int ldb, long sBb,
    long offC, int ldc, long sCb,
    int N, int K, int kChunk, int splitK,
    const float* __restrict__ bias,
    int nTerm, long dAoff, long dCoff)
{
    __shared__ float As[2][8][132];
    __shared__ float Bs[2][8][132];

    const int z = blockIdx.z;
    const int b = z / splitK;
    const int ks = z - b * splitK;
    const int kBeg = ks * kChunk;
    const int kEnd = min(K, kBeg + kChunk);
    const int nk = (kEnd - kBeg) >> 3;

    const int rowTiles = gridDim.y / nTerm;
    const int term = blockIdx.y / rowTiles;
    const int row0 = (blockIdx.y - term * rowTiles) * 128;
    const int col0 = blockIdx.x * 128;

    const float* A = Aex + offA + (long)term * dAoff;
    const float* B = g_buf + offB + (long)b * sBb;
    float* C = g_buf + offC + (long)term * dCoff + (long)z * sCb;

    const int t = threadIdx.x;
    const int arow = t >> 1, akq = (t & 1) << 2;
    const int brow = t >> 5, bcol = (t & 31) << 2;
    const int tx = t & 15, ty = t >> 4;

    const float* aPtr = A + (long)(row0 + arow) * lda + kBeg + akq;
    const float* bPtr = B + (long)(kBeg + brow) * ldb + col0 + bcol;
    const bool bIn = (col0 + bcol + 3) < N;

    float4 pa = *(const float4*)aPtr;
    float4 pb;
    if (bIn) {
        pb = *(const float4*)bPtr;
    } else {
        pb.x = (col0 + bcol + 0 < N) ? bPtr[0] : 0.0f;
        pb.y = (col0 + bcol + 1 < N) ? bPtr[1] : 0.0f;
        pb.z = (col0 + bcol + 2 < N) ? bPtr[2] : 0.0f;
        pb.w = 0.0f;
    }
    As[0][akq + 0][arow] = pa.x; As[0][akq + 1][arow] = pa.y;
    As[0][akq + 2][arow] = pa.z; As[0][akq + 3][arow] = pa.w;
    *(float4*)&Bs[0][brow][bcol] = pb;
    __syncthreads();

    float acc[8][8] = {};

    for (int kt = 0; kt < nk; kt++) {
        const int buf = kt & 1;
        if (kt + 1 < nk) {
            pa = *(const float4*)(aPtr + (kt + 1) * 8);
            const float* bp = bPtr + (long)(kt + 1) * 8 * ldb;
            if (bIn) {
                pb = *(const float4*)bp;
            } else {
                pb.x = (col0 + bcol + 0 < N) ? bp[0] : 0.0f;
                pb.y = (col0 + bcol + 1 < N) ? bp[1] : 0.0f;
                pb.z = (col0 + bcol + 2 < N) ? bp[2] : 0.0f;
                pb.w = 0.0f;
            }
        }
#pragma unroll
        for (int kk = 0; kk < 8; kk++) {
            float4 a0 = *(const float4*)&As[buf][kk][ty * 4];
            float4 a1 = *(const float4*)&As[buf][kk][64 + ty * 4];
            float4 b0 = *(const float4*)&Bs[buf][kk][tx * 4];
            float4 b1 = *(const float4*)&Bs[buf][kk][64 + tx * 4];
            float av[8] = {a0.x, a0.y, a0.z, a0.w, a1.x, a1.y, a1.z, a1.w};
            float bv[8] = {b0.x, b0.y, b0.z, b0.w, b1.x, b1.y, b1.z, b1.w};
#pragma unroll
            for (int u = 0; u < 8; u++)
#pragma unroll
                for (int v = 0; v < 8; v++)
                    acc[u][v] += av[u] * bv[v];
        }
        if (kt + 1 < nk) {
            const int nb = buf ^ 1;
            As[nb][akq + 0][arow] = pa.x; As[nb][akq + 1][arow] = pa.y;
            As[nb][akq + 2][arow] = pa.z; As[nb][akq + 3][arow] = pa.w;
            *(float4*)&Bs[nb][brow][bcol] = pb;
            __syncthreads();
        }
    }

#pragma unroll
    for (int u = 0; u < 8; u++) {
        int r = row0 + ((u < 4) ? ty * 4 + u : 64 + ty * 4 + (u - 4));
        float bz = bias ? bias[r] : 0.0f;
#pragma unroll
        for (int v = 0; v < 8; v++) {
            int c = col0 + ((v < 4) ? tx * 4 + v : 64 + tx * 4 + (v - 4));
            if (c < N) C[(long)r * ldc + c] = acc[u][v] + bz;
        }
    }
}

// ================ HMMA (mma.sync) bf16-split GEMM ==========================
// zOff: batch/split-K chunk offset; xOff: N-tile offset (column chunking).
__global__ void __launch_bounds__(256, 2) hmma_gemm_kernel(
    long offAhi, long offAlo, int lda,
    long offBhi, long offBlo, int ldb, long sBz,
    long offC, int ldc, long sCz,
    int kChunk, int batchB, int epiMode,
    long offAsub, long offAobj, const float* __restrict__ brf,
    long offRh, long offRl, int zOff, int xOff)
{
    extern __shared__ __nv_bfloat16 smb[];
    constexpr int STR = 40;
    constexpr int TILEE = 128 * STR;

    const int tid = threadIdx.x;
    const int warp = tid >> 5, lane = tid & 31;
    const int z = blockIdx.z + zOff;
    const int row0 = blockIdx.y * 128, col0 = (blockIdx.x + xOff) * 128;
    const long kBeg = batchB ? 0 : (long)z * kChunk;
    const int S = kChunk / 32;

    const __nv_bfloat16* Ahi = (const __nv_bfloat16*)(g_buf + offAhi);
    const __nv_bfloat16* Alo = (const __nv_bfloat16*)(g_buf + offAlo);
    const __nv_bfloat16* Bhi = (const __nv_bfloat16*)(g_buf + offBhi) + (batchB ? (long)z * sBz : 0);
    const __nv_bfloat16* Blo = (const __nv_bfloat16*)(g_buf + offBlo) + (batchB ? (long)z * sBz : 0);

    const int wm = (warp >> 2) * 64;
    const int wn = (warp & 3) * 32;

    float acc[4][4][4] = {};

    const uint32_t smem_base = smem_u32(smb);

    auto issue_load = [&](int s, int buf) {
        long koff = kBeg + (long)s * 32;
        uint32_t dstBase = smem_base + (uint32_t)buf * 4 * TILEE * 2;
#pragma unroll
        for (int t = 0; t < 4; t++) {
            const __nv_bfloat16* src = (t == 0) ? Ahi : (t == 1) ? Alo
                                      : (t == 2) ? Bhi : Blo;
            const int base0 = (t < 2) ? row0 : col0;
            const int ld = (t < 2) ? lda : ldb;
#pragma unroll
            for (int i = 0; i < 2; i++) {
                int idx = tid + i * 256;
                int r = idx >> 2;
                int cg = (idx & 3) * 8;
                cp_async16(dstBase + (uint32_t)((t * TILEE + r * STR + cg) * 2),
                           src + (long)(base0 + r) * ld + koff + cg);
            }
        }
        cp_commit();
    };

    issue_load(0, 0);

    for (int s = 0; s < S; s++) {
        if (s + 1 < S) {
            issue_load(s + 1, (s + 1) & 1);
            asm volatile("cp.async.wait_group 1;" ::: "memory");
        } else {
            asm volatile("cp.async.wait_group 0;" ::: "memory");
        }
        __syncthreads();

        const int buf = s & 1;
        const uint32_t tb = smem_base + (uint32_t)buf * 4 * TILEE * 2;
        const uint32_t aHiB = tb;
        const uint32_t aLoB = tb + TILEE * 2;
        const uint32_t bHiB = tb + 2 * TILEE * 2;
        const uint32_t bLoB = tb + 3 * TILEE * 2;
        const int lr = lane & 15;
        const int kofA = (lane >> 4) * 8;
        const int kofB = ((lane & 15) >> 3) * 8;

#pragma unroll
        for (int k16 = 0; k16 < 2; k16++) {
            uint32_t af[4][4], bh[4][2], bl[4][2];
#pragma unroll
            for (int mi = 0; mi < 4; mi++)
                ldsm4(af[mi], aHiB + (uint32_t)(((wm + mi * 16 + lr) * STR)
                                               + k16 * 16 + kofA) * 2);
#pragma unroll
            for (int ni = 0; ni < 4; ni++) {
                uint32_t ro = (uint32_t)(((wn + ni * 8 + (lr & 7)) * STR)
                                         + k16 * 16 + kofB) * 2;
                ldsm2(bh[ni], bHiB + ro);
                ldsm2(bl[ni], bLoB + ro);
            }
#pragma unroll
            for (int mi = 0; mi < 4; mi++)
#pragma unroll
                for (int ni = 0; ni < 4; ni++) {
                    mma16816(acc[mi][ni], af[mi], bh[ni]);   // hh
                    mma16816(acc[mi][ni], af[mi], bl[ni]);   // hl
                }
#pragma unroll
            for (int mi = 0; mi < 4; mi++)
                ldsm4(af[mi], aLoB + (uint32_t)(((wm + mi * 16 + lr) * STR)
                                               + k16 * 16 + kofA) * 2);
#pragma unroll
            for (int mi = 0; mi < 4; mi++)
#pragma unroll
                for (int ni = 0; ni < 4; ni++)
                    mma16816(acc[mi][ni], af[mi], bh[ni]);   // lh
        }
        __syncthreads();
    }

    if (epiMode == 0) {
        float* C = g_buf + offC + (long)z * sCz;
#pragma unroll
        for (int mi = 0; mi < 4; mi++) {
            int r = row0 + wm + mi * 16 + (lane >> 2);
#pragma unroll
            for (int ni = 0; ni < 4; ni++) {
                int cc = col0 + wn + ni * 8 + (lane & 3) * 2;
                *(float2*)&C[(long)r * ldc + cc] = make_float2(acc[mi][ni][0], acc[mi][ni][1]);
                *(float2*)&C[(long)(r + 8) * ldc + cc] = make_float2(acc[mi][ni][2], acc[mi][ni][3]);
            }
        }
    } else {
        using namespace sg;
        float* fs = (float*)smb;          // [128][129] floats
#pragma unroll
        for (int mi = 0; mi < 4; mi++)
#pragma unroll
            for (int half = 0; half < 2; half++) {
                int o = wm + mi * 16 + (lane >> 2) + half * 8;
#pragma unroll
                for (int ni = 0; ni < 4; ni++) {
#pragma unroll
                    for (int e = 0; e < 2; e++) {
                        int c = wn + ni * 8 + (lane & 3) * 2 + e;
                        fs[o * 129 + c] = acc[mi][ni][half * 2 + e];
                    }
                }
            }
        __syncthreads();

        const float* A1b = g_buf + offAsub + (long)z * 256 * 784;
        const float* A2b = g_buf + offAobj + (long)z * 256 * 784;
        __nv_bfloat16* rh = (__nv_bfloat16*)(g_buf + offRh) + (long)z * 256 * KFC;
        __nv_bfloat16* rl = (__nv_bfloat16*)(g_buf + offRl) + (long)z * 256 * KFC;

        const int pairLo = col0 / 49;
        const int pairHi = (col0 + 127) / 49;
        for (int p = pairLo; p <= pairHi; p++) {
            int i = p >> 4, j = p & 15;
            int sLo = max(0, col0 - p * 49);
            int sHi = min(49, col0 + 128 - p * 49);
            int len = sHi - sLo;
            int total = len * 128;
            for (int idx = tid; idx < total; idx += 256) {
                int o = idx / len;
                int s = sLo + (idx - o * len);
                int og = row0 + o;
                float v = fs[o * 129 + (p * 49 + s - col0)]
                        + A1b[(long)og * 784 + i * 49 + s]
                        + A2b[(long)og * 784 + j * 49 + s] + brf[og];
                v = fmaxf(v, 0.0f);
                __nv_bfloat16 h, l;
                split_bf16(v, h, l);
                long di = (long)p * KFC + (long)og * 49 + s;
                rh[di] = h;
                rl[di] = l;
            }
        }
    }
}

// ==================== misc data-movement / pooling =========================
__global__ void transpose_part_kernel(const float* __restrict__ input, int part)
{
    using namespace sg;
    __shared__ float tile[32][33];
    int b = blockIdx.z;
    const float* src;
    float* dst;
    int R;
    if (part == 0) {
        R = 256;
        src = input + (long)b * 256 * 384;
        dst = g_buf + OF_FEATT + (long)b * 256 * 384;
    } else {
        R = 384;
        src = g_buf + OF_RELF + (long)b * 384 * 384;
        dst = g_buf + OF_RELFT + (long)b * 384 * 384;
    }
    int r0 = blockIdx.y * 32;
    int c0 = blockIdx.x * 32;
    int tx = threadIdx.x, ty = threadIdx.y;
#pragma unroll
    for (int k = 0; k < 32; k += 8)
        tile[ty + k][tx] = src[(long)(r0 + ty + k) * 384 + c0 + tx];
    __syncthreads();
#pragma unroll
    for (int k = 0; k < 32; k += 8)
        dst[(long)(c0 + ty + k) * R + r0 + tx] = tile[tx][ty + k];
}

__global__ void __launch_bounds__(256) pool_obj_kernel(const float* __restrict__ boxes)
{
    using namespace sg;
    int b = blockIdx.y, n = blockIdx.x, tid = threadIdx.x;
    const float* bx = boxes + ((long)b * Nn + n) * 4;
    float x1 = bx[0], y1 = bx[1], x2 = bx[2], y2 = bx[3];
    float sx1 = x1 * SCALE, sy1 = y1 * SCALE, sx2 = x2 * SCALE, sy2 = y2 * SCALE;

    __shared__ float wy[7][16], wx[7][32];
    __shared__ int h0[7], h1[7], w0[7], w1[7];
    compute_weights(sx1, sy1, sx2, sy2, wy, wx, h0, h1, w0, w1, tid);

    if (tid < 49) {
        int p = tid / 7, q = tid % 7;
        float ye0 = IMGH * (float)p * (1.0f / 7.0f), ye1 = IMGH * (float)(p + 1) * (1.0f / 7.0f);
        float xe0 = IMGW * (float)q * (1.0f / 7.0f), xe1 = IMGW * (float)(q + 1) * (1.0f / 7.0f);
        float oy = fmaxf(fminf(ye1, y2) - fmaxf(ye0, y1), 0.0f);
        float ox = fmaxf(fminf(xe1, x2) - fmaxf(xe0, x1), 0.0f);
        float ch = IMGH * (1.0f / 7.0f), cw = IMGW * (1.0f / 7.0f);
        g_buf[OF_BIMAP + ((long)b * Nn + n) * PP + tid] = (oy / ch) * (ox / cw);
    }
    __syncthreads();

    float area = (sx2 - sx1) * (sy2 - sy1) * (1.0f / 49.0f);
    float inv = (area > 0.0f) ? 1.0f / fmaxf(area, 1e-9f) : 0.0f;

    int c = tid;
    const float* fb = g_buf + OF_FEATT + (long)b * HW * Cc + c;
    float acc[49];
#pragma unroll
    for (int s = 0; s < 49; s++) acc[s] = 0.0f;
    pool_channel_acc_range(fb, Cc, wy, wx, w0, h0[0], h1[6], acc);

    float* X = g_buf + OF_XOBJ + ((long)b * 512 + c) * 784 + (long)n * 49;
#pragma unroll
    for (int s = 0; s < 49; s++) X[s] = acc[s] * inv;
}

__global__ void __launch_bounds__(256) pool_ctx_kernel()
{
    using namespace sg;
    int hq = blockIdx.x, b = blockIdx.y, tid = threadIdx.x;
    __shared__ float wy[7][16], wx[7][32];
    __shared__ int h0[7], h1[7], w0[7], w1[7];
    compute_weights(0.0f, 0.0f, 24.0f, 16.0f, wy, wx, h0, h1, w0, w1, tid);
    __syncthreads();

    float inv = 49.0f / (24.0f * 16.0f);
    int c = tid;
    const float* fb = g_buf + OF_CTXF + ((long)b * Cc + c) * HW;
    float acc[49];
#pragma unroll
    for (int s = 0; s < 49; s++) acc[s] = 0.0f;
    pool_channel_acc_range(fb, 1, wy, wx, w0, hq * 4, hq * 4 + 4, acc);
    float* X = g_buf + OF_PCTX4 + (((long)b * 4 + hq) * Cc + c) * PP;
#pragma unroll
    for (int s = 0; s < 49; s++) X[s] = acc[s] * inv;
}

__global__ void pack_xobj_kernel()
{
    using namespace sg;
    int b = blockIdx.y;
    int base = blockIdx.x * blockDim.x + threadIdx.x;
    int stride = gridDim.x * blockDim.x;
    for (int idx = base; idx < 256 * 784; idx += stride) {
        int cc = idx / 784, rem = idx - cc * 784;
        int n = rem / 49, s = rem - n * 49;
        long p0 = OF_PCTX4 + ((long)b * 4 * Cc + cc) * PP + s;
        float v = g_buf[p0] + g_buf[p0 + (long)Cc * PP]
                + g_buf[p0 + 2L * Cc * PP] + g_buf[p0 + 3L * Cc * PP];
        if (cc >= 128) v *= g_buf[OF_BIMAP + ((long)b * Nn + n) * PP + s];
        g_buf[OF_XOBJ + ((long)b * 512 + 256 + cc) * 784 + rem] = v;
    }
}

// Symmetric pool_rel, image-chunked via bOff. grid(136, nB), block 384.
__global__ void __launch_bounds__(384, 2) pool_rel_kernel(const float* __restrict__ boxes,
                                                          int bOff)
{
    using namespace sg;
    extern __shared__ float stage[];
    int b = blockIdx.y + bOff, t = blockIdx.x, tid = threadIdx.x;
    int i = 0, rem = t;
    while (rem >= 16 - i) { rem -= 16 - i; i++; }
    int j = i + rem;

    const float* bi = boxes + ((long)b * Nn + i) * 4;
    const float* bj = boxes + ((long)b * Nn + j) * 4;
    float ix1 = bi[0], iy1 = bi[1], ix2 = bi[2], iy2 = bi[3];
    float jx1 = bj[0], jy1 = bj[1], jx2 = bj[2], jy2 = bj[3];
    float ux1 = fminf(ix1, jx1), uy1 = fminf(iy1, jy1);
    float ux2 = fmaxf(ix2, jx2), uy2 = fmaxf(iy2, jy2);
    float sx1 = ux1 * SCALE, sy1 = uy1 * SCALE, sx2 = ux2 * SCALE, sy2 = uy2 * SCALE;

    __shared__ float wy[7][16], wx[7][32];
    __shared__ int h0[7], h1[7], w0[7], w1[7];
    __shared__ float subm[49], objm[49];
    compute_weights(sx1, sy1, sx2, sy2, wy, wx, h0, h1, w0, w1, tid);

    if (tid < 49) {
        int p = tid / 7, q = tid - p * 7;
        float ye0 = uy1 + (uy2 - uy1) * (float)p * (1.0f / 7.0f);
        float ye1 = uy1 + (uy2 - uy1) * (float)(p + 1) * (1.0f / 7.0f);
        float xe0 = ux1 + (ux2 - ux1) * (float)q * (1.0f / 7.0f);
        float xe1 = ux1 + (ux2 - ux1) * (float)(q + 1) * (1.0f / 7.0f);
        float ch = fmaxf((uy2 - uy1) * (1.0f / 7.0f), 1e-9f);
        float cw = fmaxf((ux2 - ux1) * (1.0f / 7.0f), 1e-9f);
        float oy = fmaxf(fminf(ye1, iy2) - fmaxf(ye0, iy1), 0.0f);
        float ox = fmaxf(fminf(xe1, ix2) - fmaxf(xe0, ix1), 0.0f);
        subm[tid] = (oy / ch) * (ox / cw);
        oy = fmaxf(fminf(ye1, jy2) - fmaxf(ye0, jy1), 0.0f);
        ox = fmaxf(fminf(xe1, jx2) - fmaxf(xe0, jx1), 0.0f);
        objm[tid] = (oy / ch) * (ox / cw);
    }
    __syncthreads();

    float area = (sx2 - sx1) * (sy2 - sy1) * (1.0f / 49.0f);
    float inv = (area > 0.0f) ? 1.0f / fmaxf(area, 1e-9f) : 0.0f;

    int c = tid;
    const float* fb = g_buf + OF_RELFT + (long)b * HW * C32 + c;
    float acc[49];
#pragma unroll
    for (int s = 0; s < 49; s++) acc[s] = 0.0f;
    pool_channel_acc_range(fb, C32, wy, wx, w0, h0[0], h1[6], acc);

#pragma unroll
    for (int s = 0; s < 49; s++)
        stage[c * 49 + s] = acc[s] * inv;
    __syncthreads();

    __nv_bfloat16* xh = (__nv_bfloat16*)(g_buf + OF_XRTH);
    __nv_bfloat16* xl = (__nv_bfloat16*)(g_buf + OF_XRTL);
    int pair1 = i * 16 + j;
    int pair2 = j * 16 + i;
    long base1 = ((long)b * KFC + (long)pair1 * 49) * 384;
    long base2 = ((long)b * KFC + (long)pair2 * 49) * 384;
    for (int idx = tid; idx < 49 * 384; idx += 384) {
        int s = idx / 384, cc = idx - s * 384;
        float raw = stage[cc * 49 + s];
        float m1 = (cc < 128) ? 1.0f : (cc < 256 ? subm[s] : objm[s]);
        __nv_bfloat16 h, l;
        split_bf16(raw * m1, h, l);
        xh[base1 + (long)s * 384 + cc] = h;
        xl[base1 + (long)s * 384 + cc] = l;
        if (i != j) {
            float m2 = (cc < 128) ? 1.0f : (cc < 256 ? objm[s] : subm[s]);
            split_bf16(raw * m2, h, l);
            xh[base2 + (long)s * 384 + cc] = h;
            xl[base2 + (long)s * 384 + cc] = l;
        }
    }
}

__global__ void __launch_bounds__(256) combine_obj_kernel()
{
    using namespace sg;
    int row = blockIdx.x >> 3;
    int seg = blockIdx.x & 7;
    int b = row >> 4, i = row & 15;
    const float* obj = g_buf + OF_OBJ + (long)b * 256 * 784 + (long)i * 49;
    __nv_bfloat16* rh = (__nv_bfloat16*)(g_buf + OF_ROH) + (long)row * KFC;
    __nv_bfloat16* rl = (__nv_bfloat16*)(g_buf + OF_ROL) + (long)row * KFC;
    int beg = seg * 1568, end = beg + 1568;
    for (int idx = beg + threadIdx.x; idx < end; idx += 256) {
        int o = idx / 49, s = idx - o * 49;
        float v = fmaxf(obj[(long)o * 784 + s], 0.0f);
        __nv_bfloat16 h, l;
        split_bf16(v, h, l);
        rh[idx] = h; rl[idx] = l;
    }
}

__global__ void convert_w_kernel(const float* __restrict__ W, int lda, int colOff,
                                 long offHi, long offLo, long total, int Kout)
{
    __nv_bfloat16* ph = (__nv_bfloat16*)(g_buf + offHi);
    __nv_bfloat16* pl = (__nv_bfloat16*)(g_buf + offLo);
    for (long idx = (long)blockIdx.x * blockDim.x + threadIdx.x; idx < total;
         idx += (long)gridDim.x * blockDim.x) {
        long m = idx / Kout;
        int k = (int)(idx - m * Kout);
        float x = W[m * lda + colOff + k];
        __nv_bfloat16 h, l;
        split_bf16(x, h, l);
        ph[idx] = h; pl[idx] = l;
    }
}

__global__ void reduce_split_kernel(long offP, long offO, long MN, int Ncols,
                                    int S, const float* __restrict__ bias)
{
    long idx = (long)blockIdx.x * blockDim.x + threadIdx.x;
    if (idx >= MN) return;
    float s = 0.0f;
    for (int i = 0; i < S; i++) s += g_buf[offP + (long)i * MN + idx];
    int m = (int)(idx / Ncols);
    g_buf[offO + idx] = s + bias[m];
}

__global__ void finalize_kernel(long srcOff, int ncols, float* __restrict__ out)
{
    int col = blockIdx.x, n = threadIdx.x;
    float v = g_buf[srcOff + (long)n * ncols + col];
    float s = v * v;
#pragma unroll
    for (int o = 16; o > 0; o >>= 1) s += __shfl_xor_sync(0xffffffffu, s, o);
    __shared__ float red[8];
    if ((n & 31) == 0) red[n >> 5] = s;
    __syncthreads();
    float tot = red[0] + red[1] + red[2] + red[3] + red[4] + red[5] + red[6] + red[7];
    out[(long)col * 256 + n] = v / sqrtf(tot);
}

// ===========================================================================
extern "C" void kernel_launch(void* const* d_in, const int* in_sizes, int n_in,
                              void* d_out, int out_size)
{
    using namespace sg;
    const float* input = (const float*)d_in[0];
    const float* boxes = (const float*)d_in[1];
    const float* W_ctx = (const float*)d_in[3];
    const float* b_ctx = (const float*)d_in[4];
    const float* W_rel = (const float*)d_in[5];
    const float* b_rel = (const float*)d_in[6];
    const float* W_of  = (const float*)d_in[7];
    const float* b_of  = (const float*)d_in[8];
    const float* W_rf  = (const float*)d_in[9];
    const float* b_rf  = (const float*)d_in[10];
    const float* W_ofc = (const float*)d_in[11];
    const float* b_ofc = (const float*)d_in[12];
    const float* W_rfc = (const float*)d_in[13];
    const float* b_rfc = (const float*)d_in[14];
    float* out = (float*)d_out;

    const long s784  = 256L * 784;
    const int SMEM_HMMA = 2 * 4 * 128 * 40 * 2;   // 81920 bytes

    // One-time setup on first (pre-capture) call; handles reused thereafter.
    struct Ctx {
        cudaStream_t s1, s2, sG;
        cudaEvent_t e0, eCtx, eWP, eW, eA, ePA, ePB, eObjDone, eGDone;
        Ctx() {
            cudaStreamCreateWithFlags(&s1, cudaStreamNonBlocking);
            cudaStreamCreateWithFlags(&s2, cudaStreamNonBlocking);
            cudaStreamCreateWithFlags(&sG, cudaStreamNonBlocking);
            cudaEventCreateWithFlags(&e0,      cudaEventDisableTiming);
            cudaEventCreateWithFlags(&eCtx,    cudaEventDisableTiming);
            cudaEventCreateWithFlags(&eWP,     cudaEventDisableTiming);
            cudaEventCreateWithFlags(&eW,      cudaEventDisableTiming);
            cudaEventCreateWithFlags(&eA,      cudaEventDisableTiming);
            cudaEventCreateWithFlags(&ePA,     cudaEventDisableTiming);
            cudaEventCreateWithFlags(&ePB,     cudaEventDisableTiming);
            cudaEventCreateWithFlags(&eObjDone, cudaEventDisableTiming);
            cudaEventCreateWithFlags(&eGDone,  cudaEventDisableTiming);
            cudaFuncSetAttribute(hmma_gemm_kernel,
                cudaFuncAttributeMaxDynamicSharedMemorySize, 2 * 4 * 128 * 40 * 2);
            cudaFuncSetAttribute(pool_rel_kernel,
                cudaFuncAttributeMaxDynamicSharedMemorySize, 384 * 49 * 4);
        }
    };
    static Ctx ctx;
    cudaStream_t s1 = ctx.s1, s2 = ctx.s2, sG = ctx.sG;

    cudaEventRecord(ctx.e0, 0);
    cudaStreamWaitEvent(s1, ctx.e0, 0);
    cudaStreamWaitEvent(s2, ctx.e0, 0);
    cudaStreamWaitEvent(sG, ctx.e0, 0);

    // ---- stream 0: rel chain, chunked ----
    conv_dual_kernel<<<dim3(6, 4, 8), 256, 0, 0>>>(input, W_ctx, b_ctx, W_rel, b_rel, 0);
    cudaEventRecord(ctx.eCtx, 0);
    conv_dual_kernel<<<dim3(6, 6, 8), 256, 0, 0>>>(input, W_ctx, b_ctx, W_rel, b_rel, 4);
    transpose_part_kernel<<<dim3(12, 12, 8), dim3(32, 8), 0, 0>>>(input, 1);
    pool_rel_kernel<<<dim3(NPAIRU, 4), 384, 384 * 49 * 4, 0>>>(boxes, 0);
    cudaEventRecord(ctx.ePA, 0);
    pool_rel_kernel<<<dim3(NPAIRU, 4), 384, 384 * 49 * 4, 0>>>(boxes, 4);
    cudaEventRecord(ctx.ePB, 0);

    // ---- s2: weight conversions (pair weights first -> eWP) ----
    convert_w_kernel<<<384, 256, 0, s2>>>(W_rf, 896, 512, OF_WPH, OF_WPL, 256L * 384, 384);
    cudaEventRecord(ctx.eWP, s2);
    convert_w_kernel<<<4096, 256, 0, s2>>>(W_rfc, KFC, 0, OF_WRH, OF_WRL, 256L * KFC, KFC);
    convert_w_kernel<<<4096, 256, 0, s2>>>(W_ofc, KFC, 0, OF_WOH, OF_WOL, 256L * KFC, KFC);
    cudaEventRecord(ctx.eW, s2);

    // ---- s1: obj chain ----
    transpose_part_kernel<<<dim3(12, 8, 8), dim3(32, 8), 0, s1>>>(input, 0);
    pool_obj_kernel<<<dim3(16, 8), 256, 0, s1>>>(boxes);
    cudaStreamWaitEvent(s1, ctx.eCtx, 0);
    pool_ctx_kernel<<<dim3(4, 8), 256, 0, s1>>>();
    pack_xobj_kernel<<<dim3(16, 8), 256, 0, s1>>>();
    sgemm128_kernel<<<dim3(7, 2, 8), 256, 0, s1>>>(W_of, 0, 512, OF_XOBJ, 784, 512L * 784,
                                                   OF_OBJ, 784, s784, 784, 512, 512, 1, b_of,
                                                   1, 0, 0);
    sgemm128_kernel<<<dim3(7, 4, 8), 256, 0, s1>>>(W_rf, 0, 896, OF_OBJ, 784, s784,
                                                   OF_ASUB, 784, s784, 784, 256, 256, 1, nullptr,
                                                   2, 256, OF_AOBJ - OF_ASUB);
    cudaEventRecord(ctx.eA, s1);
    combine_obj_kernel<<<1024, 256, 0, s1>>>();
    cudaStreamWaitEvent(s1, ctx.eW, 0);
    hmma_gemm_kernel<<<dim3(1, 2, SPLKO), 256, SMEM_HMMA, s1>>>(
        OF_WOH, OF_WOL, KFC, OF_ROH, OF_ROL, KFC, 0,
        OF_FPO, 128, 256L * 128, KFC / SPLKO, 0, 0, 0, 0, nullptr, 0, 0, 0, 0);
    reduce_split_kernel<<<128, 256, 0, s1>>>(OF_FPO, OF_FOBJ, 256L * 128, 128, SPLKO, b_ofc);
    finalize_kernel<<<128, 256, 0, s1>>>(OF_FOBJ, 128, out);
    cudaEventRecord(ctx.eObjDone, s1);

    // ---- sG: big-GEMM chain, image/column chunked ----
    cudaStreamWaitEvent(sG, ctx.eWP, 0);
    cudaStreamWaitEvent(sG, ctx.eA, 0);
    cudaStreamWaitEvent(sG, ctx.ePA, 0);
    hmma_gemm_kernel<<<dim3(98, 2, 4), 256, SMEM_HMMA, sG>>>(          // images 0-3
        OF_WPH, OF_WPL, 384, OF_XRTH, OF_XRTL, 384, (long)KFC * 384,
        0, 0, 0, 384, 1, 1, OF_ASUB, OF_AOBJ, b_rf, OF_RTH, OF_RTL, 0, 0);
    cudaStreamWaitEvent(sG, ctx.ePB, 0);
    hmma_gemm_kernel<<<dim3(98, 2, 4), 256, SMEM_HMMA, sG>>>(          // images 4-7
        OF_WPH, OF_WPL, 384, OF_XRTH, OF_XRTL, 384, (long)KFC * 384,
        0, 0, 0, 384, 1, 1, OF_ASUB, OF_AOBJ, b_rf, OF_RTH, OF_RTL, 4, 0);
    cudaStreamWaitEvent(sG, ctx.eW, 0);
    hmma_gemm_kernel<<<dim3(8, 2, SPLK), 256, SMEM_HMMA, sG>>>(        // rel FC cols 0-1023
        OF_WRH, OF_WRL, KFC, OF_RTH, OF_RTL, KFC, 0,
        OF_FP, 2048, 256L * 2048, KFC / SPLK, 0, 0, 0, 0, nullptr, 0, 0, 0, 0);
    hmma_gemm_kernel<<<dim3(8, 2, SPLK), 256, SMEM_HMMA, sG>>>(        // rel FC cols 1024-2047
        OF_WRH, OF_WRL, KFC, OF_RTH, OF_RTL, KFC, 0,
        OF_FP, 2048, 256L * 2048, KFC / SPLK, 0, 0, 0, 0, nullptr, 0, 0, 0, 8);
    reduce_split_kernel<<<2048, 256, 0, sG>>>(OF_FP, OF_FREL, 256L * 2048, 2048, SPLK, b_rfc);
    finalize_kernel<<<2048, 256, 0, sG>>>(OF_FREL, 2048, out + 32768);
    cudaEventRecord(ctx.eGDone, sG);

    // ---- join on the capture stream ----
    cudaStreamWaitEvent(0, ctx.eGDone, 0);
    cudaStreamWaitEvent(0, ctx.eObjDone, 0);
}

// round 17
// speedup vs baseline: 1.1124x; 1.1124x over previous
#include <cuda_runtime.h>
#include <cuda_bf16.h>
#include <math.h>
#include <stdint.h>

namespace sg {
constexpr int Bn = 8, Cc = 256, Nn = 16;
constexpr int HW = 384;
constexpr int C32 = 384;
constexpr float SCALE = 1.0f / 16.0f;
constexpr float IMGW = 384.0f, IMGH = 256.0f;
constexpr int PP = 49;
constexpr int KFC = 12544;
constexpr int SPLK = 7;               // rel FC split-K (7*1792 = 12544)
constexpr int SPLKO = 49;
constexpr int NPAIRU = 136;

constexpr long SZ_CTXF  = (long)Bn * Cc * HW;
constexpr long SZ_RELF  = (long)Bn * C32 * HW;
constexpr long SZ_FEATT = SZ_CTXF;
constexpr long SZ_RELFT = SZ_RELF;
constexpr long SZ_PCTX4 = (long)Bn * 4 * Cc * PP;
constexpr long SZ_BIMAP = (long)Bn * Nn * PP;
constexpr long SZ_XOBJ  = (long)Bn * 512 * 784;
constexpr long SZ_OBJ   = (long)Bn * 256 * 784;
constexpr long SZ_ASUB  = SZ_OBJ;
constexpr long SZ_AOBJ  = SZ_OBJ;
constexpr long SZ_FREL  = 256L * 2048;
constexpr long SZ_FOBJ  = 256L * 128;
constexpr long SZ_FP    = 14L * 256 * 2048;
constexpr long SZ_FPO   = (long)SPLKO * 256 * 128;
constexpr long FU_WP  = 256L * 384 / 2;
constexpr long FU_XRT = (long)Bn * KFC * 384 / 2;
constexpr long FU_WR  = 256L * KFC / 2;
constexpr long FU_RT  = 2048L * KFC / 2;
constexpr long FU_WO  = FU_WR;
constexpr long FU_RO  = 128L * KFC / 2;

constexpr long OF_CTXF  = 0;
constexpr long OF_RELF  = OF_CTXF  + SZ_CTXF;
constexpr long OF_FEATT = OF_RELF  + SZ_RELF;
constexpr long OF_RELFT = OF_FEATT + SZ_FEATT;
constexpr long OF_PCTX4 = OF_RELFT + SZ_RELFT;
constexpr long OF_BIMAP = OF_PCTX4 + SZ_PCTX4;
constexpr long OF_XOBJ  = OF_BIMAP + SZ_BIMAP;
constexpr long OF_OBJ   = OF_XOBJ  + SZ_XOBJ;
constexpr long OF_ASUB  = OF_OBJ   + SZ_OBJ;
constexpr long OF_AOBJ  = OF_ASUB  + SZ_ASUB;
constexpr long OF_FREL  = OF_AOBJ  + SZ_AOBJ;
constexpr long OF_FOBJ  = OF_FREL  + SZ_FREL;
constexpr long OF_FP    = OF_FOBJ  + SZ_FOBJ;
constexpr long OF_FPO   = OF_FP    + SZ_FP;
constexpr long OF_WPH   = OF_FPO   + SZ_FPO;
constexpr long OF_WPL   = OF_WPH   + FU_WP;
constexpr long OF_XRTH  = OF_WPL   + FU_WP;
constexpr long OF_XRTL  = OF_XRTH  + FU_XRT;
constexpr long OF_WRH   = OF_XRTL  + FU_XRT;
constexpr long OF_WRL   = OF_WRH   + FU_WR;
constexpr long OF_RTH   = OF_WRL   + FU_WR;
constexpr long OF_RTL   = OF_RTH   + FU_RT;
constexpr long OF_WOH   = OF_RTL   + FU_RT;
constexpr long OF_WOL   = OF_WOH   + FU_WO;
constexpr long OF_ROH   = OF_WOL   + FU_WO;
constexpr long OF_ROL   = OF_ROH   + FU_RO;
constexpr long TOTAL    = OF_ROL   + FU_RO + 64;
}  // namespace sg

__device__ float g_buf[sg::TOTAL];

// ========================= low-level helpers ===============================
__device__ __forceinline__ uint32_t smem_u32(const void* p) {
    uint32_t a;
    asm("{ .reg .u64 t; cvta.to.shared.u64 t, %1; cvt.u32.u64 %0, t; }" : "=r"(a) : "l"(p));
    return a;
}
__device__ __forceinline__ void cp_async16(uint32_t dst, const void* src) {
    asm volatile("cp.async.cg.shared.global [%0], [%1], 16;" :: "r"(dst), "l"(src));
}
__device__ __forceinline__ void cp_commit() {
    asm volatile("cp.async.commit_group;" ::: "memory");
}
__device__ __forceinline__ void ldsm4(uint32_t* a, uint32_t addr) {
    asm volatile("ldmatrix.sync.aligned.m8n8.x4.shared.b16 {%0,%1,%2,%3}, [%4];"
        : "=r"(a[0]), "=r"(a[1]), "=r"(a[2]), "=r"(a[3]) : "r"(addr));
}
__device__ __forceinline__ void ldsm2(uint32_t* b, uint32_t addr) {
    asm volatile("ldmatrix.sync.aligned.m8n8.x2.shared.b16 {%0,%1}, [%2];"
        : "=r"(b[0]), "=r"(b[1]) : "r"(addr));
}
__device__ __forceinline__ void mma16816(float* d, const uint32_t* a, const uint32_t* b) {
    asm volatile("mma.sync.aligned.m16n8k16.row.col.f32.bf16.bf16.f32 "
        "{%0,%1,%2,%3}, {%4,%5,%6,%7}, {%8,%9}, {%0,%1,%2,%3};"
        : "+f"(d[0]), "+f"(d[1]), "+f"(d[2]), "+f"(d[3])
        : "r"(a[0]), "r"(a[1]), "r"(a[2]), "r"(a[3]), "r"(b[0]), "r"(b[1]));
}
__device__ __forceinline__ void split_bf16(float x, __nv_bfloat16& h, __nv_bfloat16& l) {
    h = __float2bfloat16(x);
    l = __float2bfloat16(x - __bfloat162float(h));
}

// ========================= PrRoI pooling helpers ===========================
static __device__ __forceinline__ float hatG(float t) {
    float tl = fminf(fmaxf(t, -1.0f), 0.0f);
    float tr = fminf(fmaxf(t, 0.0f), 1.0f);
    return 0.5f * (tl + 1.0f) * (tl + 1.0f) + 0.5f - 0.5f * (1.0f - tr) * (1.0f - tr);
}

static __device__ __forceinline__ void compute_weights(
    float x1, float y1, float x2, float y2,
    float (*wy)[16], float (*wx)[32],
    int* h0, int* h1, int* w0, int* w1, int tid)
{
    if (tid < 112) {
        int p = tid / 16, i = tid % 16;
        float e0 = y1 + (y2 - y1) * (float)p * (1.0f / 7.0f);
        float e1 = y1 + (y2 - y1) * (float)(p + 1) * (1.0f / 7.0f);
        wy[p][i] = hatG(e1 - (float)i) - hatG(e0 - (float)i);
    }
    if (tid < 224) {
        int q = tid >> 5, i = tid & 31;
        float v = 0.0f;
        if (i < 24) {
            float e0 = x1 + (x2 - x1) * (float)q * (1.0f / 7.0f);
            float e1 = x1 + (x2 - x1) * (float)(q + 1) * (1.0f / 7.0f);
            v = hatG(e1 - (float)i) - hatG(e0 - (float)i);
        }
        wx[q][i] = v;
    }
    if (tid < 7) {
        float e0 = y1 + (y2 - y1) * (float)tid * (1.0f / 7.0f);
        float e1 = y1 + (y2 - y1) * (float)(tid + 1) * (1.0f / 7.0f);
        h0[tid] = max(0, (int)ceilf(e0) - 1);
        h1[tid] = min(16, (int)floorf(e1) + 2);
    }
    if (tid >= 32 && tid < 39) {
        int q = tid - 32;
        float e0 = x1 + (x2 - x1) * (float)q * (1.0f / 7.0f);
        float e1 = x1 + (x2 - x1) * (float)(q + 1) * (1.0f / 7.0f);
        w0[q] = max(0, (int)ceilf(e0) - 1);
        w1[q] = min(24, (int)floorf(e1) + 2);
    }
}

static __device__ __forceinline__ void pool_channel_acc_range(
    const float* __restrict__ fb, int ps,
    const float (*wy)[16], const float (*wx)[32],
    const int* w0,
    int hlo, int hhi, float* acc)
{
    for (int h = hlo; h < hhi; h++) {
        const float* row = fb + (long)h * 24 * ps;
        float colsum[7];
#pragma unroll
        for (int q = 0; q < 7; q++) {
            int base = w0[q];
            const float* rp = row + (long)base * ps;
            float a = 0.0f;
#pragma unroll
            for (int k = 0; k < 6; k++)
                a += wx[q][base + k] * rp[(long)k * ps];
            colsum[q] = a;
        }
#pragma unroll
        for (int p = 0; p < 7; p++) {
            float wv = wy[p][h];
#pragma unroll
            for (int q = 0; q < 7; q++)
                acc[p * 7 + q] += wv * colsum[q];
        }
    }
}

// ===================== dual 1x1 conv (yOff-chunked) ========================
__global__ void __launch_bounds__(256) conv_dual_kernel(
    const float* __restrict__ input,
    const float* __restrict__ Wctx, const float* __restrict__ bctx,
    const float* __restrict__ Wrel, const float* __restrict__ brel,
    int yOff)
{
    using namespace sg;
    __shared__ float As[16][65];
    __shared__ float Bs[16][68];

    const int b = blockIdx.z;
    const int tid = threadIdx.x;
    const int row0 = (blockIdx.y + yOff) * 64;
    const int col0 = blockIdx.x * 64;
    const bool isCtx = row0 < 256;
    const float* A = isCtx ? (Wctx + (long)row0 * 256)
                           : (Wrel + (long)(row0 - 256) * 256);
    const float* bias = isCtx ? bctx : brel;
    const int biasBase = isCtx ? row0 : row0 - 256;
    const float* Bm = input + (long)b * Cc * HW;
    float* Cm = isCtx ? (g_buf + OF_CTXF + (long)b * Cc * HW + (long)row0 * 384)
                      : (g_buf + OF_RELF + (long)b * C32 * HW + (long)(row0 - 256) * 384);

    const int ty = tid >> 4, tx = tid & 15;
    const int ty4 = ty * 4, tx4 = tx * 4;
    const int ar = tid >> 2, ak = (tid & 3) << 2;
    const int br = tid >> 4, bc = (tid & 15) << 2;

    float acc[4][4] = {};

    for (int k0 = 0; k0 < 256; k0 += 16) {
        float4 av = *(const float4*)(A + (long)ar * 256 + k0 + ak);
        As[ak + 0][ar] = av.x; As[ak + 1][ar] = av.y;
        As[ak + 2][ar] = av.z; As[ak + 3][ar] = av.w;
        float4 bv = *(const float4*)(Bm + (long)(k0 + br) * 384 + col0 + bc);
        *(float4*)&Bs[br][bc] = bv;
        __syncthreads();

#pragma unroll
        for (int k = 0; k < 16; k++) {
            float a0 = As[k][ty4 + 0], a1 = As[k][ty4 + 1];
            float a2 = As[k][ty4 + 2], a3 = As[k][ty4 + 3];
            float4 b4 = *(const float4*)&Bs[k][tx4];
            acc[0][0] += a0 * b4.x; acc[0][1] += a0 * b4.y; acc[0][2] += a0 * b4.z; acc[0][3] += a0 * b4.w;
            acc[1][0] += a1 * b4.x; acc[1][1] += a1 * b4.y; acc[1][2] += a1 * b4.z; acc[1][3] += a1 * b4.w;
            acc[2][0] += a2 * b4.x; acc[2][1] += a2 * b4.y; acc[2][2] += a2 * b4.z; acc[2][3] += a2 * b4.w;
            acc[3][0] += a3 * b4.x; acc[3][1] += a3 * b4.y; acc[3][2] += a3 * b4.z; acc[3][3] += a3 * b4.w;
        }
        __syncthreads();
    }

#pragma unroll
    for (int u = 0; u < 4; u++) {
        float bz = bias[biasBase + ty4 + u];
#pragma unroll
        for (int v = 0; v < 4; v++)
            Cm[(long)(ty4 + u) * 384 + col0 + tx4 + v] = acc[u][v] + bz;
    }
}

// fp32 128x128 GEMM, optional multi-term via grid.y folding.
__global__ void __launch_bounds__(256) sgemm128_kernel(
    const float* __restrict__ Aex, long offA, int lda,
    long offB, int ldb, long sBb,
    long offC, int ldc, long sCb,
    int N, int K, int kChunk, int splitK,
    const float* __restrict__ bias,
    int nTerm, long dAoff, long dCoff)
{
    __shared__ float As[2][8][132];
    __shared__ float Bs[2][8][132];

    const int z = blockIdx.z;
    const int b = z / splitK;
    const int ks = z - b * splitK;
    const int kBeg = ks * kChunk;
    const int kEnd = min(K, kBeg + kChunk);
    const int nk = (kEnd - kBeg) >> 3;

    const int rowTiles = gridDim.y / nTerm;
    const int term = blockIdx.y / rowTiles;
    const int row0 = (blockIdx.y - term * rowTiles) * 128;
    const int col0 = blockIdx.x * 128;

    const float* A = Aex + offA + (long)term * dAoff;
    const float* B = g_buf + offB + (long)b * sBb;
    float* C = g_buf + offC + (long)term * dCoff + (long)z * sCb;

    const int t = threadIdx.x;
    const int arow = t >> 1, akq = (t & 1) << 2;
    const int brow = t >> 5, bcol = (t & 31) << 2;
    const int tx = t & 15, ty = t >> 4;

    const float* aPtr = A + (long)(row0 + arow) * lda + kBeg + akq;
    const float* bPtr = B + (long)(kBeg + brow) * ldb + col0 + bcol;
    const bool bIn = (col0 + bcol + 3) < N;

    float4 pa = *(const float4*)aPtr;
    float4 pb;
    if (bIn) {
        pb = *(const float4*)bPtr;
    } else {
        pb.x = (col0 + bcol + 0 < N) ? bPtr[0] : 0.0f;
        pb.y = (col0 + bcol + 1 < N) ? bPtr[1] : 0.0f;
        pb.z = (col0 + bcol + 2 < N) ? bPtr[2] : 0.0f;
        pb.w = 0.0f;
    }
    As[0][akq + 0][arow] = pa.x; As[0][akq + 1][arow] = pa.y;
    As[0][akq + 2][arow] = pa.z; As[0][akq + 3][arow] = pa.w;
    *(float4*)&Bs[0][brow][bcol] = pb;
    __syncthreads();

    float acc[8][8] = {};

    for (int kt = 0; kt < nk; kt++) {
        const int buf = kt & 1;
        if (kt + 1 < nk) {
            pa = *(const float4*)(aPtr + (kt + 1) * 8);
            const float* bp = bPtr + (long)(kt + 1) * 8 * ldb;
            if (bIn) {
                pb = *(const float4*)bp;
            } else {
                pb.x = (col0 + bcol + 0 < N) ? bp[0] : 0.0f;
                pb.y = (col0 + bcol + 1 < N) ? bp[1] : 0.0f;
                pb.z = (col0 + bcol + 2 < N) ? bp[2] : 0.0f;
                pb.w = 0.0f;
            }
        }
#pragma unroll
        for (int kk = 0; kk < 8; kk++) {
            float4 a0 = *(const float4*)&As[buf][kk][ty * 4];
            float4 a1 = *(const float4*)&As[buf][kk][64 + ty * 4];
            float4 b0 = *(const float4*)&Bs[buf][kk][tx * 4];
            float4 b1 = *(const float4*)&Bs[buf][kk][64 + tx * 4];
            float av[8] = {a0.x, a0.y, a0.z, a0.w, a1.x, a1.y, a1.z, a1.w};
            float bv[8] = {b0.x, b0.y, b0.z, b0.w, b1.x, b1.y, b1.z, b1.w};
#pragma unroll
            for (int u = 0; u < 8; u++)
#pragma unroll
                for (int v = 0; v < 8; v++)
                    acc[u][v] += av[u] * bv[v];
        }
        if (kt + 1 < nk) {
            const int nb = buf ^ 1;
            As[nb][akq + 0][arow] = pa.x; As[nb][akq + 1][arow] = pa.y;
            As[nb][akq + 2][arow] = pa.z; As[nb][akq + 3][arow] = pa.w;
            *(float4*)&Bs[nb][brow][bcol] = pb;
            __syncthreads();
        }
    }

#pragma unroll
    for (int u = 0; u < 8; u++) {
        int r = row0 + ((u < 4) ? ty * 4 + u : 64 + ty * 4 + (u - 4));
        float bz = bias ? bias[r] : 0.0f;
#pragma unroll
        for (int v = 0; v < 8; v++) {
            int c = col0 + ((v < 4) ? tx * 4 + v : 64 + tx * 4 + (v - 4));
            if (c < N) C[(long)r * ldc + c] = acc[u][v] + bz;
        }
    }
}

// ================ HMMA (mma.sync) bf16-split GEMM ==========================
__global__ void __launch_bounds__(256, 2) hmma_gemm_kernel(
    long offAhi, long offAlo, int lda,
    long offBhi, long offBlo, int ldb, long sBz,
    long offC, int ldc, long sCz,
    int kChunk, int batchB, int epiMode,
    long offAsub, long offAobj, const float* __restrict__ brf,
    long offRh, long offRl)
{
    extern __shared__ __nv_bfloat16 smb[];
    constexpr int STR = 40;
    constexpr int TILEE = 128 * STR;

    const int tid = threadIdx.x;
    const int warp = tid >> 5, lane = tid & 31;
    const int z = blockIdx.z;
    const int row0 = blockIdx.y * 128, col0 = blockIdx.x * 128;
    const long kBeg = batchB ? 0 : (long)z * kChunk;
    const int S = kChunk / 32;

    const __nv_bfloat16* Ahi = (const __nv_bfloat16*)(g_buf + offAhi);
    const __nv_bfloat16* Alo = (const __nv_bfloat16*)(g_buf + offAlo);
    const __nv_bfloat16* Bhi = (const __nv_bfloat16*)(g_buf + offBhi) + (batchB ? (long)z * sBz : 0);
    const __nv_bfloat16* Blo = (const __nv_bfloat16*)(g_buf + offBlo) + (batchB ? (long)z * sBz : 0);

    const int wm = (warp >> 2) * 64;
    const int wn = (warp & 3) * 32;

    float acc[4][4][4] = {};

    const uint32_t smem_base = smem_u32(smb);

    auto issue_load = [&](int s, int buf) {
        long koff = kBeg + (long)s * 32;
        uint32_t dstBase = smem_base + (uint32_t)buf * 4 * TILEE * 2;
#pragma unroll
        for (int t = 0; t < 4; t++) {
            const __nv_bfloat16* src = (t == 0) ? Ahi : (t == 1) ? Alo
                                      : (t == 2) ? Bhi : Blo;
            const int base0 = (t < 2) ? row0 : col0;
            const int ld = (t < 2) ? lda : ldb;
#pragma unroll
            for (int i = 0; i < 2; i++) {
                int idx = tid + i * 256;
                int r = idx >> 2;
                int cg = (idx & 3) * 8;
                cp_async16(dstBase + (uint32_t)((t * TILEE + r * STR + cg) * 2),
                           src + (long)(base0 + r) * ld + koff + cg);
            }
        }
        cp_commit();
    };

    issue_load(0, 0);

    for (int s = 0; s < S; s++) {
        if (s + 1 < S) {
            issue_load(s + 1, (s + 1) & 1);
            asm volatile("cp.async.wait_group 1;" ::: "memory");
        } else {
            asm volatile("cp.async.wait_group 0;" ::: "memory");
        }
        __syncthreads();

        const int buf = s & 1;
        const uint32_t tb = smem_base + (uint32_t)buf * 4 * TILEE * 2;
        const uint32_t aHiB = tb;
        const uint32_t aLoB = tb + TILEE * 2;
        const uint32_t bHiB = tb + 2 * TILEE * 2;
        const uint32_t bLoB = tb + 3 * TILEE * 2;
        const int lr = lane & 15;
        const int kofA = (lane >> 4) * 8;
        const int kofB = ((lane & 15) >> 3) * 8;

#pragma unroll
        for (int k16 = 0; k16 < 2; k16++) {
            uint32_t af[4][4], bh[4][2], bl[4][2];
#pragma unroll
            for (int mi = 0; mi < 4; mi++)
                ldsm4(af[mi], aHiB + (uint32_t)(((wm + mi * 16 + lr) * STR)
                                               + k16 * 16 + kofA) * 2);
#pragma unroll
            for (int ni = 0; ni < 4; ni++) {
                uint32_t ro = (uint32_t)(((wn + ni * 8 + (lr & 7)) * STR)
                                         + k16 * 16 + kofB) * 2;
                ldsm2(bh[ni], bHiB + ro);
                ldsm2(bl[ni], bLoB + ro);
            }
#pragma unroll
            for (int mi = 0; mi < 4; mi++)
#pragma unroll
                for (int ni = 0; ni < 4; ni++) {
                    mma16816(acc[mi][ni], af[mi], bh[ni]);   // hh
                    mma16816(acc[mi][ni], af[mi], bl[ni]);   // hl
                }
#pragma unroll
            for (int mi = 0; mi < 4; mi++)
                ldsm4(af[mi], aLoB + (uint32_t)(((wm + mi * 16 + lr) * STR)
                                               + k16 * 16 + kofA) * 2);
#pragma unroll
            for (int mi = 0; mi < 4; mi++)
#pragma unroll
                for (int ni = 0; ni < 4; ni++)
                    mma16816(acc[mi][ni], af[mi], bh[ni]);   // lh
        }
        __syncthreads();
    }

    if (epiMode == 0) {
        float* C = g_buf + offC + (long)z * sCz;
#pragma unroll
        for (int mi = 0; mi < 4; mi++) {
            int r = row0 + wm + mi * 16 + (lane >> 2);
#pragma unroll
            for (int ni = 0; ni < 4; ni++) {
                int cc = col0 + wn + ni * 8 + (lane & 3) * 2;
                *(float2*)&C[(long)r * ldc + cc] = make_float2(acc[mi][ni][0], acc[mi][ni][1]);
                *(float2*)&C[(long)(r + 8) * ldc + cc] = make_float2(acc[mi][ni][2], acc[mi][ni][3]);
            }
        }
    } else {
        using namespace sg;
        float* fs = (float*)smb;          // [128][129] floats
#pragma unroll
        for (int mi = 0; mi < 4; mi++)
#pragma unroll
            for (int half = 0; half < 2; half++) {
                int o = wm + mi * 16 + (lane >> 2) + half * 8;
#pragma unroll
                for (int ni = 0; ni < 4; ni++) {
#pragma unroll
                    for (int e = 0; e < 2; e++) {
                        int c = wn + ni * 8 + (lane & 3) * 2 + e;
                        fs[o * 129 + c] = acc[mi][ni][half * 2 + e];
                    }
                }
            }
        __syncthreads();

        const float* A1b = g_buf + offAsub + (long)z * 256 * 784;
        const float* A2b = g_buf + offAobj + (long)z * 256 * 784;
        __nv_bfloat16* rh = (__nv_bfloat16*)(g_buf + offRh) + (long)z * 256 * KFC;
        __nv_bfloat16* rl = (__nv_bfloat16*)(g_buf + offRl) + (long)z * 256 * KFC;

        const int pairLo = col0 / 49;
        const int pairHi = (col0 + 127) / 49;
        for (int p = pairLo; p <= pairHi; p++) {
            int i = p >> 4, j = p & 15;
            int sLo = max(0, col0 - p * 49);
            int sHi = min(49, col0 + 128 - p * 49);
            int len = sHi - sLo;
            int total = len * 128;
            for (int idx = tid; idx < total; idx += 256) {
                int o = idx / len;
                int s = sLo + (idx - o * len);
                int og = row0 + o;
                float v = fs[o * 129 + (p * 49 + s - col0)]
                        + A1b[(long)og * 784 + i * 49 + s]
                        + A2b[(long)og * 784 + j * 49 + s] + brf[og];
                v = fmaxf(v, 0.0f);
                __nv_bfloat16 h, l;
                split_bf16(v, h, l);
                long di = (long)p * KFC + (long)og * 49 + s;
                rh[di] = h;
                rl[di] = l;
            }
        }
    }
}

// ==================== misc data-movement / pooling =========================
__global__ void transpose_part_kernel(const float* __restrict__ input, int part)
{
    using namespace sg;
    __shared__ float tile[32][33];
    int b = blockIdx.z;
    const float* src;
    float* dst;
    int R;
    if (part == 0) {
        R = 256;
        src = input + (long)b * 256 * 384;
        dst = g_buf + OF_FEATT + (long)b * 256 * 384;
    } else {
        R = 384;
        src = g_buf + OF_RELF + (long)b * 384 * 384;
        dst = g_buf + OF_RELFT + (long)b * 384 * 384;
    }
    int r0 = blockIdx.y * 32;
    int c0 = blockIdx.x * 32;
    int tx = threadIdx.x, ty = threadIdx.y;
#pragma unroll
    for (int k = 0; k < 32; k += 8)
        tile[ty + k][tx] = src[(long)(r0 + ty + k) * 384 + c0 + tx];
    __syncthreads();
#pragma unroll
    for (int k = 0; k < 32; k += 8)
        dst[(long)(c0 + ty + k) * R + r0 + tx] = tile[tx][ty + k];
}

__global__ void __launch_bounds__(256) pool_obj_kernel(const float* __restrict__ boxes)
{
    using namespace sg;
    int b = blockIdx.y, n = blockIdx.x, tid = threadIdx.x;
    const float* bx = boxes + ((long)b * Nn + n) * 4;
    float x1 = bx[0], y1 = bx[1], x2 = bx[2], y2 = bx[3];
    float sx1 = x1 * SCALE, sy1 = y1 * SCALE, sx2 = x2 * SCALE, sy2 = y2 * SCALE;

    __shared__ float wy[7][16], wx[7][32];
    __shared__ int h0[7], h1[7], w0[7], w1[7];
    compute_weights(sx1, sy1, sx2, sy2, wy, wx, h0, h1, w0, w1, tid);

    if (tid < 49) {
        int p = tid / 7, q = tid % 7;
        float ye0 = IMGH * (float)p * (1.0f / 7.0f), ye1 = IMGH * (float)(p + 1) * (1.0f / 7.0f);
        float xe0 = IMGW * (float)q * (1.0f / 7.0f), xe1 = IMGW * (float)(q + 1) * (1.0f / 7.0f);
        float oy = fmaxf(fminf(ye1, y2) - fmaxf(ye0, y1), 0.0f);
        float ox = fmaxf(fminf(xe1, x2) - fmaxf(xe0, x1), 0.0f);
        float ch = IMGH * (1.0f / 7.0f), cw = IMGW * (1.0f / 7.0f);
        g_buf[OF_BIMAP + ((long)b * Nn + n) * PP + tid] = (oy / ch) * (ox / cw);
    }
    __syncthreads();

    float area = (sx2 - sx1) * (sy2 - sy1) * (1.0f / 49.0f);
    float inv = (area > 0.0f) ? 1.0f / fmaxf(area, 1e-9f) : 0.0f;

    int c = tid;
    const float* fb = g_buf + OF_FEATT + (long)b * HW * Cc + c;
    float acc[49];
#pragma unroll
    for (int s = 0; s < 49; s++) acc[s] = 0.0f;
    pool_channel_acc_range(fb, Cc, wy, wx, w0, h0[0], h1[6], acc);

    float* X = g_buf + OF_XOBJ + ((long)b * 512 + c) * 784 + (long)n * 49;
#pragma unroll
    for (int s = 0; s < 49; s++) X[s] = acc[s] * inv;
}

__global__ void __launch_bounds__(256) pool_ctx_kernel()
{
    using namespace sg;
    int hq = blockIdx.x, b = blockIdx.y, tid = threadIdx.x;
    __shared__ float wy[7][16], wx[7][32];
    __shared__ int h0[7], h1[7], w0[7], w1[7];
    compute_weights(0.0f, 0.0f, 24.0f, 16.0f, wy, wx, h0, h1, w0, w1, tid);
    __syncthreads();

    float inv = 49.0f / (24.0f * 16.0f);
    int c = tid;
    const float* fb = g_buf + OF_CTXF + ((long)b * Cc + c) * HW;
    float acc[49];
#pragma unroll
    for (int s = 0; s < 49; s++) acc[s] = 0.0f;
    pool_channel_acc_range(fb, 1, wy, wx, w0, hq * 4, hq * 4 + 4, acc);
    float* X = g_buf + OF_PCTX4 + (((long)b * 4 + hq) * Cc + c) * PP;
#pragma unroll
    for (int s = 0; s < 49; s++) X[s] = acc[s] * inv;
}

__global__ void pack_xobj_kernel()
{
    using namespace sg;
    int b = blockIdx.y;
    int base = blockIdx.x * blockDim.x + threadIdx.x;
    int stride = gridDim.x * blockDim.x;
    for (int idx = base; idx < 256 * 784; idx += stride) {
        int cc = idx / 784, rem = idx - cc * 784;
        int n = rem / 49, s = rem - n * 49;
        long p0 = OF_PCTX4 + ((long)b * 4 * Cc + cc) * PP + s;
        float v = g_buf[p0] + g_buf[p0 + (long)Cc * PP]
                + g_buf[p0 + 2L * Cc * PP] + g_buf[p0 + 3L * Cc * PP];
        if (cc >= 128) v *= g_buf[OF_BIMAP + ((long)b * Nn + n) * PP + s];
        g_buf[OF_XOBJ + ((long)b * 512 + 256 + cc) * 784 + rem] = v;
    }
}

// Symmetric pool_rel. grid(136, 8), block 384.
__global__ void __launch_bounds__(384, 2) pool_rel_kernel(const float* __restrict__ boxes)
{
    using namespace sg;
    extern __shared__ float stage[];
    int b = blockIdx.y, t = blockIdx.x, tid = threadIdx.x;
    int i = 0, rem = t;
    while (rem >= 16 - i) { rem -= 16 - i; i++; }
    int j = i + rem;

    const float* bi = boxes + ((long)b * Nn + i) * 4;
    const float* bj = boxes + ((long)b * Nn + j) * 4;
    float ix1 = bi[0], iy1 = bi[1], ix2 = bi[2], iy2 = bi[3];
    float jx1 = bj[0], jy1 = bj[1], jx2 = bj[2], jy2 = bj[3];
    float ux1 = fminf(ix1, jx1), uy1 = fminf(iy1, jy1);
    float ux2 = fmaxf(ix2, jx2), uy2 = fmaxf(iy2, jy2);
    float sx1 = ux1 * SCALE, sy1 = uy1 * SCALE, sx2 = ux2 * SCALE, sy2 = uy2 * SCALE;

    __shared__ float wy[7][16], wx[7][32];
    __shared__ int h0[7], h1[7], w0[7], w1[7];
    __shared__ float subm[49], objm[49];
    compute_weights(sx1, sy1, sx2, sy2, wy, wx, h0, h1, w0, w1, tid);

    if (tid < 49) {
        int p = tid / 7, q = tid - p * 7;
        float ye0 = uy1 + (uy2 - uy1) * (float)p * (1.0f / 7.0f);
        float ye1 = uy1 + (uy2 - uy1) * (float)(p + 1) * (1.0f / 7.0f);
        float xe0 = ux1 + (ux2 - ux1) * (float)q * (1.0f / 7.0f);
        float xe1 = ux1 + (ux2 - ux1) * (float)(q + 1) * (1.0f / 7.0f);
        float ch = fmaxf((uy2 - uy1) * (1.0f / 7.0f), 1e-9f);
        float cw = fmaxf((ux2 - ux1) * (1.0f / 7.0f), 1e-9f);
        float oy = fmaxf(fminf(ye1, iy2) - fmaxf(ye0, iy1), 0.0f);
        float ox = fmaxf(fminf(xe1, ix2) - fmaxf(xe0, ix1), 0.0f);
        subm[tid] = (oy / ch) * (ox / cw);
        oy = fmaxf(fminf(ye1, jy2) - fmaxf(ye0, jy1), 0.0f);
        ox = fmaxf(fminf(xe1, jx2) - fmaxf(xe0, jx1), 0.0f);
        objm[tid] = (oy / ch) * (ox / cw);
    }
    __syncthreads();

    float area = (sx2 - sx1) * (sy2 - sy1) * (1.0f / 49.0f);
    float inv = (area > 0.0f) ? 1.0f / fmaxf(area, 1e-9f) : 0.0f;

    int c = tid;
    const float* fb = g_buf + OF_RELFT + (long)b * HW * C32 + c;
    float acc[49];
#pragma unroll
    for (int s = 0; s < 49; s++) acc[s] = 0.0f;
    pool_channel_acc_range(fb, C32, wy, wx, w0, h0[0], h1[6], acc);

#pragma unroll
    for (int s = 0; s < 49; s++)
        stage[c * 49 + s] = acc[s] * inv;
    __syncthreads();

    __nv_bfloat16* xh = (__nv_bfloat16*)(g_buf + OF_XRTH);
    __nv_bfloat16* xl = (__nv_bfloat16*)(g_buf + OF_XRTL);
    int pair1 = i * 16 + j;
    int pair2 = j * 16 + i;
    long base1 = ((long)b * KFC + (long)pair1 * 49) * 384;
    long base2 = ((long)b * KFC + (long)pair2 * 49) * 384;
    for (int idx = tid; idx < 49 * 384; idx += 384) {
        int s = idx / 384, cc = idx - s * 384;
        float raw = stage[cc * 49 + s];
        float m1 = (cc < 128) ? 1.0f : (cc < 256 ? subm[s] : objm[s]);
        __nv_bfloat16 h, l;
        split_bf16(raw * m1, h, l);
        xh[base1 + (long)s * 384 + cc] = h;
        xl[base1 + (long)s * 384 + cc] = l;
        if (i != j) {
            float m2 = (cc < 128) ? 1.0f : (cc < 256 ? objm[s] : subm[s]);
            split_bf16(raw * m2, h, l);
            xh[base2 + (long)s * 384 + cc] = h;
            xl[base2 + (long)s * 384 + cc] = l;
        }
    }
}

__global__ void __launch_bounds__(256) combine_obj_kernel()
{
    using namespace sg;
    int row = blockIdx.x >> 3;
    int seg = blockIdx.x & 7;
    int b = row >> 4, i = row & 15;
    const float* obj = g_buf + OF_OBJ + (long)b * 256 * 784 + (long)i * 49;
    __nv_bfloat16* rh = (__nv_bfloat16*)(g_buf + OF_ROH) + (long)row * KFC;
    __nv_bfloat16* rl = (__nv_bfloat16*)(g_buf + OF_ROL) + (long)row * KFC;
    int beg = seg * 1568, end = beg + 1568;
    for (int idx = beg + threadIdx.x; idx < end; idx += 256) {
        int o = idx / 49, s = idx - o * 49;
        float v = fmaxf(obj[(long)o * 784 + s], 0.0f);
        __nv_bfloat16 h, l;
        split_bf16(v, h, l);
        rh[idx] = h; rl[idx] = l;
    }
}

__global__ void convert_w_kernel(const float* __restrict__ W, int lda, int colOff,
                                 long offHi, long offLo, long total, int Kout)
{
    __nv_bfloat16* ph = (__nv_bfloat16*)(g_buf + offHi);
    __nv_bfloat16* pl = (__nv_bfloat16*)(g_buf + offLo);
    for (long idx = (long)blockIdx.x * blockDim.x + threadIdx.x; idx < total;
         idx += (long)gridDim.x * blockDim.x) {
        long m = idx / Kout;
        int k = (int)(idx - m * Kout);
        float x = W[m * lda + colOff + k];
        __nv_bfloat16 h, l;
        split_bf16(x, h, l);
        ph[idx] = h; pl[idx] = l;
    }
}

__global__ void reduce_split_kernel(long offP, long offO, long MN, int Ncols,
                                    int S, const float* __restrict__ bias)
{
    long idx = (long)blockIdx.x * blockDim.x + threadIdx.x;
    if (idx >= MN) return;
    float s = 0.0f;
    for (int i = 0; i < S; i++) s += g_buf[offP + (long)i * MN + idx];
    int m = (int)(idx / Ncols);
    g_buf[offO + idx] = s + bias[m];
}

__global__ void finalize_kernel(long srcOff, int ncols, float* __restrict__ out)
{
    int col = blockIdx.x, n = threadIdx.x;
    float v = g_buf[srcOff + (long)n * ncols + col];
    float s = v * v;
#pragma unroll
    for (int o = 16; o > 0; o >>= 1) s += __shfl_xor_sync(0xffffffffu, s, o);
    __shared__ float red[8];
    if ((n & 31) == 0) red[n >> 5] = s;
    __syncthreads();
    float tot = red[0] + red[1] + red[2] + red[3] + red[4] + red[5] + red[6] + red[7];
    out[(long)col * 256 + n] = v / sqrtf(tot);
}

// ===========================================================================
extern "C" void kernel_launch(void* const* d_in, const int* in_sizes, int n_in,
                              void* d_out, int out_size)
{
    using namespace sg;
    const float* input = (const float*)d_in[0];
    const float* boxes = (const float*)d_in[1];
    const float* W_ctx = (const float*)d_in[3];
    const float* b_ctx = (const float*)d_in[4];
    const float* W_rel = (const float*)d_in[5];
    const float* b_rel = (const float*)d_in[6];
    const float* W_of  = (const float*)d_in[7];
    const float* b_of  = (const float*)d_in[8];
    const float* W_rf  = (const float*)d_in[9];
    const float* b_rf  = (const float*)d_in[10];
    const float* W_ofc = (const float*)d_in[11];
    const float* b_ofc = (const float*)d_in[12];
    const float* W_rfc = (const float*)d_in[13];
    const float* b_rfc = (const float*)d_in[14];
    float* out = (float*)d_out;

    const long s784  = 256L * 784;
    const int SMEM_HMMA = 2 * 4 * 128 * 40 * 2;   // 81920 bytes

    // One-time setup on first (pre-capture) call; handles reused thereafter.
    struct Ctx {
        cudaStream_t s1, s2;
        cudaEvent_t e0, eCtx, eW, eA, eObjDone;
        Ctx() {
            cudaStreamCreateWithFlags(&s1, cudaStreamNonBlocking);
            cudaStreamCreateWithFlags(&s2, cudaStreamNonBlocking);
            cudaEventCreateWithFlags(&e0,      cudaEventDisableTiming);
            cudaEventCreateWithFlags(&eCtx,    cudaEventDisableTiming);
            cudaEventCreateWithFlags(&eW,      cudaEventDisableTiming);
            cudaEventCreateWithFlags(&eA,      cudaEventDisableTiming);
            cudaEventCreateWithFlags(&eObjDone, cudaEventDisableTiming);
            cudaFuncSetAttribute(hmma_gemm_kernel,
                cudaFuncAttributeMaxDynamicSharedMemorySize, 2 * 4 * 128 * 40 * 2);
            cudaFuncSetAttribute(pool_rel_kernel,
                cudaFuncAttributeMaxDynamicSharedMemorySize, 384 * 49 * 4);
        }
    };
    static Ctx ctx;
    cudaStream_t s1 = ctx.s1, s2 = ctx.s2;

    cudaEventRecord(ctx.e0, 0);
    cudaStreamWaitEvent(s1, ctx.e0, 0);
    cudaStreamWaitEvent(s2, ctx.e0, 0);

    // ---- stream 0: rel-feature chain (conv split: ctx rows first) ----
    conv_dual_kernel<<<dim3(6, 4, 8), 256, 0, 0>>>(input, W_ctx, b_ctx, W_rel, b_rel, 0);
    cudaEventRecord(ctx.eCtx, 0);
    conv_dual_kernel<<<dim3(6, 6, 8), 256, 0, 0>>>(input, W_ctx, b_ctx, W_rel, b_rel, 4);
    convert_w_kernel<<<384, 256, 0, s2>>>(W_rf, 896, 512, OF_WPH, OF_WPL, 256L * 384, 384);
    transpose_part_kernel<<<dim3(12, 12, 8), dim3(32, 8), 0, 0>>>(input, 1);
    pool_rel_kernel<<<dim3(NPAIRU, 8), 384, 384 * 49 * 4, 0>>>(boxes);

    // ---- s2: remaining weight conversions ----
    convert_w_kernel<<<4096, 256, 0, s2>>>(W_rfc, KFC, 0, OF_WRH, OF_WRL, 256L * KFC, KFC);
    convert_w_kernel<<<4096, 256, 0, s2>>>(W_ofc, KFC, 0, OF_WOH, OF_WOL, 256L * KFC, KFC);
    cudaEventRecord(ctx.eW, s2);

    // ---- s1: obj chain ----
    transpose_part_kernel<<<dim3(12, 8, 8), dim3(32, 8), 0, s1>>>(input, 0);
    pool_obj_kernel<<<dim3(16, 8), 256, 0, s1>>>(boxes);
    cudaStreamWaitEvent(s1, ctx.eCtx, 0);
    pool_ctx_kernel<<<dim3(4, 8), 256, 0, s1>>>();
    pack_xobj_kernel<<<dim3(16, 8), 256, 0, s1>>>();
    sgemm128_kernel<<<dim3(7, 2, 8), 256, 0, s1>>>(W_of, 0, 512, OF_XOBJ, 784, 512L * 784,
                                                   OF_OBJ, 784, s784, 784, 512, 512, 1, b_of,
                                                   1, 0, 0);
    sgemm128_kernel<<<dim3(7, 4, 8), 256, 0, s1>>>(W_rf, 0, 896, OF_OBJ, 784, s784,
                                                   OF_ASUB, 784, s784, 784, 256, 256, 1, nullptr,
                                                   2, 256, OF_AOBJ - OF_ASUB);
    cudaEventRecord(ctx.eA, s1);
    combine_obj_kernel<<<1024, 256, 0, s1>>>();
    cudaStreamWaitEvent(s1, ctx.eW, 0);
    hmma_gemm_kernel<<<dim3(1, 2, SPLKO), 256, SMEM_HMMA, s1>>>(
        OF_WOH, OF_WOL, KFC, OF_ROH, OF_ROL, KFC, 0,
        OF_FPO, 128, 256L * 128, KFC / SPLKO, 0, 0, 0, 0, nullptr, 0, 0);
    reduce_split_kernel<<<128, 256, 0, s1>>>(OF_FPO, OF_FOBJ, 256L * 128, 128, SPLKO, b_ofc);
    finalize_kernel<<<128, 256, 0, s1>>>(OF_FOBJ, 128, out);
    cudaEventRecord(ctx.eObjDone, s1);

    // ---- stream 0: big GEMMs ----
    cudaStreamWaitEvent(0, ctx.eA, 0);
    cudaStreamWaitEvent(0, ctx.eW, 0);
    hmma_gemm_kernel<<<dim3(98, 2, 8), 256, SMEM_HMMA, 0>>>(
        OF_WPH, OF_WPL, 384, OF_XRTH, OF_XRTL, 384, (long)KFC * 384,
        0, 0, 0, 384, 1, 1, OF_ASUB, OF_AOBJ, b_rf, OF_RTH, OF_RTL);
    hmma_gemm_kernel<<<dim3(16, 2, SPLK), 256, SMEM_HMMA, 0>>>(
        OF_WRH, OF_WRL, KFC, OF_RTH, OF_RTL, KFC, 0,
        OF_FP, 2048, 256L * 2048, KFC / SPLK, 0, 0, 0, 0, nullptr, 0, 0);
    reduce_split_kernel<<<2048, 256, 0, 0>>>(OF_FP, OF_FREL, 256L * 2048, 2048, SPLK, b_rfc);
    finalize_kernel<<<2048, 256, 0, 0>>>(OF_FREL, 2048, out + 32768);
    cudaStreamWaitEvent(0, ctx.eObjDone, 0);
}